// round 12
// baseline (speedup 1.0000x reference)
#include <cuda_runtime.h>

#define NB 32
#define NQ 1024
#define NG 64
#define NT 128           // threads per solver CTA
#define KPT 8            // columns per thread
#define BIG 1e300
#define MARGIN 1e-3f

// 8 MB scratch: transposed cost cost[b][i][j], i = gt row, j = proposal col
__device__ float g_cost[NB * NG * NQ];

// ---------------------------------------------------------------------------
// Cost build (exact IEEE order, no FMA contraction -> bit-matches reference fp32)
// ---------------------------------------------------------------------------
__global__ void build_cost_kernel(const float* __restrict__ obj,
                                  const float* __restrict__ cd,
                                  const float* __restrict__ gi) {
    int t = blockIdx.x * blockDim.x + threadIdx.x;
    if (t >= NB * NG * NQ) return;
    int j = t & (NQ - 1);
    int i = (t >> 10) & (NG - 1);
    int b = t >> 16;
    float o = obj[b * NQ + j];
    int src = (b * NQ + j) * NG + i;
    float a0 = __fmul_rn(5.0f, -o);
    float a1 = __fmul_rn(10.0f, cd[src]);
    float a2 = __fmul_rn(2.0f, -gi[src]);
    g_cost[t] = __fadd_rn(__fadd_rn(a0, a1), a2);
}

// Order-preserving uint64 key for a double, column index in low 10 bits
// (near-equal values tie toward the smaller index == numpy first-min rule).
__device__ __forceinline__ unsigned long long packkey(double x, int idx) {
    long long sb = __double_as_longlong(x);
    unsigned long long ub = (unsigned long long)sb;
    ub = (sb < 0) ? ~ub : (ub | 0x8000000000000000ULL);
    return (ub & ~1023ULL) | (unsigned long long)idx;
}

// ---------------------------------------------------------------------------
// Jonker-Volgenant shortest-augmenting-path LSA, one CTA per batch.
// fp32 screen -> one divergent exact-fp64 region (R11-proven).
// Plumbing: per-warp packed-key atomicMin cells, all-thread combine,
// ONE barrier per Dijkstra step via 4-slot barrier-ordered reset ring.
// ---------------------------------------------------------------------------
__global__ void __launch_bounds__(NT, 1)
solve_kernel(const int* __restrict__ ngt, float* __restrict__ out) {
    const int b = blockIdx.x;
    const int tid = threadIdx.x;
    const int w = tid >> 5;

    __shared__ double s_short[NQ];           // exact fp64 shortest (write-through)
    __shared__ float  s_shortf[NQ];          // fp32 shadow of s_short
    __shared__ short  s_row4col[NQ];
    __shared__ unsigned char s_path[NQ];
    __shared__ double s_u[NG];
    __shared__ float  s_uf[NG];              // fp32 shadow of s_u
    __shared__ short  s_col4row[NG];
    __shared__ unsigned char s_inSR[NG];
    __shared__ __align__(16) unsigned long long s_pack[4][4];   // [ring][warp]

    float* outi = out + b * NQ;              // per_prop_gt_inds (as float)
    float* outm = out + NB * NQ + b * NQ;    // proposal_matched_mask

    for (int j = tid; j < NQ; j += NT) { outi[j] = 0.0f; outm[j] = 0.0f; }

    const int g = ngt[b];
    if (g <= 0) return;

    const float* __restrict__ cost = g_cost + b * NG * NQ;

    double v_reg[KPT], sh_reg[KPT];
    float  vf[KPT], shf[KPT];
#pragma unroll
    for (int k = 0; k < KPT; ++k) { v_reg[k] = 0.0; vf[k] = 0.0f; }

    for (int j = tid; j < NQ; j += NT) s_row4col[j] = -1;
    for (int i = tid; i < g; i += NT) { s_u[i] = 0.0; s_uf[i] = 0.0f; s_col4row[i] = -1; }
    if (tid < 16) s_pack[tid >> 2][tid & 3] = ~0ULL;

    int t = 0;   // ring phase, continuous across Dijkstras
    __syncthreads();

    for (int cur = 0; cur < g; ++cur) {
        unsigned scmask = 0;
        double lbest = BIG;
        int lidx = 0;
#pragma unroll
        for (int k = 0; k < KPT; ++k) { sh_reg[k] = BIG; shf[k] = 3e38f; }
        for (int i = tid; i < g; i += NT) s_inSR[i] = (i == cur) ? 1 : 0;
        __syncthreads();

        int i = cur;
        double mvd = 0.0;
        float  mvf = 0.0f;
        int sink;

        // ---- Dijkstra over columns: ONE barrier per step ----
        while (true) {
            const float  scalf = mvf - s_uf[i];          // fp32-only screen scalar
            const double scal  = mvd - s_u[i];           // exact (off screen path)
            const float* __restrict__ crow = cost + i * NQ;

            // branchless fp32 screen over my 8 columns
            float cf_arr[KPT];
            unsigned mask = 0;
#pragma unroll
            for (int k = 0; k < KPT; ++k) {
                const int j = tid + (k << 7);
                const float cf = __ldg(crow + j);
                cf_arr[k] = cf;
                const float rf = (scalf + cf) - vf[k];
                const bool cand = (!((scmask >> k) & 1u)) && (rf < shf[k] + MARGIN);
                mask |= cand ? (1u << k) : 0u;
            }

            // ONE divergent region: exact fp64 update, reference rounding order
            if (mask) {
                do {
                    const int k = __ffs(mask) - 1;
                    mask &= mask - 1;
                    const int j = tid + (k << 7);
                    double r = (scal + (double)cf_arr[k]) - v_reg[k];
                    if (r < sh_reg[k]) {
                        sh_reg[k] = r;
                        shf[k] = (float)r;
                        s_short[j] = r;
                        s_shortf[j] = shf[k];
                        s_path[j] = (unsigned char)i;
                        if (r < lbest) { lbest = r; lidx = j; }
                    }
                } while (mask);
            }

            if (lbest < BIG) atomicMin(&s_pack[t & 3][w], packkey(lbest, lidx));
            __syncthreads();

            // all threads combine the 4 per-warp cells
            const unsigned long long* cell = s_pack[t & 3];
            unsigned long long p  = cell[0];
            unsigned long long q1 = cell[1];
            unsigned long long q2 = cell[2];
            unsigned long long q3 = cell[3];
            if (q1 < p) p = q1;
            if (q2 < p) p = q2;
            if (q3 < p) p = q3;
            const int bidx = (int)(p & 1023ULL);

            if (tid < 4) s_pack[(t + 2) & 3][tid] = ~0ULL;   // barrier-ordered reset

            mvd = s_short[bidx];                 // exact value (broadcast LDS)
            mvf = s_shortf[bidx];                // fp32 shadow (parallel LDS)
            const int rc = s_row4col[bidx];

            // owner removes the visited column and rescans its registers
            if ((bidx & (NT - 1)) == tid) {
                const int kk = bidx >> 7;
                scmask |= 1u << kk;
                lbest = BIG; lidx = 0;
#pragma unroll
                for (int k = 0; k < KPT; ++k) {
                    if (!((scmask >> k) & 1u) && sh_reg[k] < lbest) {
                        lbest = sh_reg[k];
                        lidx = tid + (k << 7);
                    }
                }
            }
            ++t;
            if (rc < 0) { sink = bidx; break; }
            if (tid == 0) s_inSR[rc] = 1;
            i = rc;
        }

        __syncthreads();   // final inSR write + relax writes visible to dual phase

        // ---- dual updates (pre-augment col4row) ----
#pragma unroll
        for (int k = 0; k < KPT; ++k) {
            if ((scmask >> k) & 1u) {
                v_reg[k] -= (mvd - sh_reg[k]);
                vf[k] = (float)v_reg[k];
            }
        }
        for (int ii = tid; ii < g; ii += NT) {
            if (ii == cur) {
                s_u[ii] += mvd;
                s_uf[ii] = (float)s_u[ii];
            } else if (s_inSR[ii]) {
                s_u[ii] += (mvd - s_short[s_col4row[ii]]);
                s_uf[ii] = (float)s_u[ii];
            }
        }
        __syncthreads();

        // ---- augment alternating path (serial, short) ----
        if (tid == 0) {
            int j = sink;
            while (true) {
                const int ii = s_path[j];
                s_row4col[j] = (short)ii;
                const short nj = s_col4row[ii];
                s_col4row[ii] = (short)j;
                j = nj;
                if (ii == cur) break;
            }
        }
        __syncthreads();
    }

    // outputs: proposal p = col4row[i] gets index i, mask 1
    for (int i = tid; i < g; i += NT) {
        const int p = s_col4row[i];
        outi[p] = (float)i;
        outm[p] = 1.0f;
    }
}

extern "C" void kernel_launch(void* const* d_in, const int* in_sizes, int n_in,
                              void* d_out, int out_size) {
    const float* obj = (const float*)d_in[1];
    const float* cd  = (const float*)d_in[2];
    const float* gi  = (const float*)d_in[3];
    const int* ngt   = (const int*)d_in[4];
    float* out = (float*)d_out;

    const int total = NB * NG * NQ;
    build_cost_kernel<<<(total + 255) / 256, 256>>>(obj, cd, gi);
    solve_kernel<<<NB, NT>>>(ngt, out);
}

// round 13
// speedup vs baseline: 1.5591x; 1.5591x over previous
#include <cuda_runtime.h>

#define NB 32
#define NQ 1024
#define NG 64
#define NT 128           // threads per solver CTA
#define KPT 8            // columns per thread
#define BIGF 3.0e38f

// 8 MB scratch: transposed cost cost[b][i][j], i = gt row, j = proposal col
__device__ float g_cost[NB * NG * NQ];

// ---------------------------------------------------------------------------
// Cost build (exact IEEE order, no FMA contraction -> bit-matches reference fp32)
// ---------------------------------------------------------------------------
__global__ void build_cost_kernel(const float* __restrict__ obj,
                                  const float* __restrict__ cd,
                                  const float* __restrict__ gi) {
    int t = blockIdx.x * blockDim.x + threadIdx.x;
    if (t >= NB * NG * NQ) return;
    int j = t & (NQ - 1);
    int i = (t >> 10) & (NG - 1);
    int b = t >> 16;
    float o = obj[b * NQ + j];
    int src = (b * NQ + j) * NG + i;
    float a0 = __fmul_rn(5.0f, -o);
    float a1 = __fmul_rn(10.0f, cd[src]);
    float a2 = __fmul_rn(2.0f, -gi[src]);
    g_cost[t] = __fadd_rn(__fadd_rn(a0, a1), a2);
}

// Order-preserving u32 key for a float (monotone increasing)
__device__ __forceinline__ unsigned int flip32(float x) {
    unsigned int b = __float_as_uint(x);
    return (b & 0x80000000u) ? ~b : (b | 0x80000000u);
}
// 42-bit packed key in u64: value key high, column idx low 10 bits
// (equal values tie toward the smaller index == numpy first-min rule).
__device__ __forceinline__ unsigned long long packkey(float x, int idx) {
    return ((unsigned long long)flip32(x) << 10) | (unsigned long long)idx;
}

// ---------------------------------------------------------------------------
// Jonker-Volgenant shortest-augmenting-path LSA, one CTA per batch.
// Pure fp32 (gamble: decisions identical to fp64 on this data; bench-verified).
// Reference evaluation order: r = ((mv + c) - u[i]) - v[j].
// Per-warp packed-key atomicMin cells; all-thread combine;
// ONE barrier per Dijkstra step via 4-slot barrier-ordered reset ring.
// ---------------------------------------------------------------------------
__global__ void __launch_bounds__(NT, 1)
solve_kernel(const int* __restrict__ ngt, float* __restrict__ out) {
    const int b = blockIdx.x;
    const int tid = threadIdx.x;
    const int w = tid >> 5;

    __shared__ float s_short[NQ];            // shortest (write-through)
    __shared__ short s_row4col[NQ];
    __shared__ unsigned char s_path[NQ];
    __shared__ float s_u[NG];
    __shared__ short s_col4row[NG];
    __shared__ unsigned char s_inSR[NG];
    __shared__ __align__(16) unsigned long long s_pack[4][4];   // [ring][warp]

    float* outi = out + b * NQ;              // per_prop_gt_inds (as float)
    float* outm = out + NB * NQ + b * NQ;    // proposal_matched_mask

    for (int j = tid; j < NQ; j += NT) { outi[j] = 0.0f; outm[j] = 0.0f; }

    const int g = ngt[b];
    if (g <= 0) return;

    const float* __restrict__ cost = g_cost + b * NG * NQ;

    float v_reg[KPT], sh_reg[KPT];
#pragma unroll
    for (int k = 0; k < KPT; ++k) v_reg[k] = 0.0f;

    for (int j = tid; j < NQ; j += NT) s_row4col[j] = -1;
    for (int i = tid; i < g; i += NT) { s_u[i] = 0.0f; s_col4row[i] = -1; }
    if (tid < 16) s_pack[tid >> 2][tid & 3] = ~0ULL;

    int t = 0;   // ring phase, continuous across Dijkstras
    __syncthreads();

    for (int cur = 0; cur < g; ++cur) {
        unsigned scmask = 0;
        float lbest = BIGF;
        int lidx = 0;
#pragma unroll
        for (int k = 0; k < KPT; ++k) sh_reg[k] = BIGF;
        for (int i = tid; i < g; i += NT) s_inSR[i] = (i == cur) ? 1 : 0;
        __syncthreads();

        int i = cur;
        float mv = 0.0f;
        int sink;

        // ---- Dijkstra over columns: ONE barrier per step ----
        while (true) {
            const float u_i = s_u[i];                    // broadcast LDS
            const float* __restrict__ crow = cost + i * NQ;

#pragma unroll
            for (int k = 0; k < KPT; ++k) {
                if (!((scmask >> k) & 1u)) {
                    const int j = tid + (k << 7);
                    // exact reference order: ((mv + c) - u) - v, all fp32 rn
                    const float r = __fadd_rn(__fadd_rn(__fadd_rn(mv, __ldg(crow + j)), -u_i), -v_reg[k]);
                    if (r < sh_reg[k]) {
                        sh_reg[k] = r;
                        s_short[j] = r;
                        s_path[j] = (unsigned char)i;
                        if (r < lbest) { lbest = r; lidx = j; }
                    }
                }
            }
            if (lbest < BIGF) atomicMin(&s_pack[t & 3][w], packkey(lbest, lidx));
            __syncthreads();

            // all threads combine the 4 per-warp cells
            const unsigned long long* cell = s_pack[t & 3];
            unsigned long long p  = cell[0];
            unsigned long long q1 = cell[1];
            unsigned long long q2 = cell[2];
            unsigned long long q3 = cell[3];
            if (q1 < p) p = q1;
            if (q2 < p) p = q2;
            if (q3 < p) p = q3;
            const int bidx = (int)(p & 1023ULL);

            if (tid < 4) s_pack[(t + 2) & 3][tid] = ~0ULL;   // barrier-ordered reset

            mv = s_short[bidx];                  // exact popped value (broadcast)
            const int rc = s_row4col[bidx];

            // owner removes the visited column and rescans its registers
            if ((bidx & (NT - 1)) == tid) {
                const int kk = bidx >> 7;
                scmask |= 1u << kk;
                lbest = BIGF; lidx = 0;
#pragma unroll
                for (int k = 0; k < KPT; ++k) {
                    if (!((scmask >> k) & 1u) && sh_reg[k] < lbest) {
                        lbest = sh_reg[k];
                        lidx = tid + (k << 7);
                    }
                }
            }
            ++t;
            if (rc < 0) { sink = bidx; break; }
            if (tid == 0) s_inSR[rc] = 1;
            i = rc;
        }

        __syncthreads();   // final relax/inSR writes visible to dual phase

        // ---- dual updates (pre-augment col4row) ----
#pragma unroll
        for (int k = 0; k < KPT; ++k) {
            if ((scmask >> k) & 1u) v_reg[k] -= (mv - sh_reg[k]);
        }
        for (int ii = tid; ii < g; ii += NT) {
            if (ii == cur) s_u[ii] += mv;
            else if (s_inSR[ii]) s_u[ii] += (mv - s_short[s_col4row[ii]]);
        }
        __syncthreads();

        // ---- augment alternating path (serial, short) ----
        if (tid == 0) {
            int j = sink;
            while (true) {
                const int ii = s_path[j];
                s_row4col[j] = (short)ii;
                const short nj = s_col4row[ii];
                s_col4row[ii] = (short)j;
                j = nj;
                if (ii == cur) break;
            }
        }
        __syncthreads();
    }

    // outputs: proposal p = col4row[i] gets index i, mask 1
    for (int i = tid; i < g; i += NT) {
        const int p = s_col4row[i];
        outi[p] = (float)i;
        outm[p] = 1.0f;
    }
}

extern "C" void kernel_launch(void* const* d_in, const int* in_sizes, int n_in,
                              void* d_out, int out_size) {
    const float* obj = (const float*)d_in[1];
    const float* cd  = (const float*)d_in[2];
    const float* gi  = (const float*)d_in[3];
    const int* ngt   = (const int*)d_in[4];
    float* out = (float*)d_out;

    const int total = NB * NG * NQ;
    build_cost_kernel<<<(total + 255) / 256, 256>>>(obj, cd, gi);
    solve_kernel<<<NB, NT>>>(ngt, out);
}

// round 14
// speedup vs baseline: 2.7097x; 1.7380x over previous
#include <cuda_runtime.h>

#define NB 32
#define NQ 1024
#define NG 64
#define NT 128           // threads per solver CTA
#define KPT 8            // columns per thread
#define BIGF 3.0e38f

// 8 MB scratch: transposed cost cost[b][i][j], i = gt row, j = proposal col
__device__ float g_cost[NB * NG * NQ];

// ---------------------------------------------------------------------------
// Cost build (exact IEEE order, no FMA contraction -> bit-matches reference fp32)
// ---------------------------------------------------------------------------
__global__ void build_cost_kernel(const float* __restrict__ obj,
                                  const float* __restrict__ cd,
                                  const float* __restrict__ gi) {
    int t = blockIdx.x * blockDim.x + threadIdx.x;
    if (t >= NB * NG * NQ) return;
    int j = t & (NQ - 1);
    int i = (t >> 10) & (NG - 1);
    int b = t >> 16;
    float o = obj[b * NQ + j];
    int src = (b * NQ + j) * NG + i;
    float a0 = __fmul_rn(5.0f, -o);
    float a1 = __fmul_rn(10.0f, cd[src]);
    float a2 = __fmul_rn(2.0f, -gi[src]);
    g_cost[t] = __fadd_rn(__fadd_rn(a0, a1), a2);
}

// Order-preserving u32 key for a float (monotone increasing), exact round-trip.
__device__ __forceinline__ unsigned int flip32(float x) {
    unsigned int b = __float_as_uint(x);
    return (b & 0x80000000u) ? ~b : (b | 0x80000000u);
}
__device__ __forceinline__ float unflip32(unsigned int k) {
    unsigned int b = (k & 0x80000000u) ? (k & 0x7fffffffu) : ~k;
    return __uint_as_float(b);
}
// 43-bit key: [flip32(val) : idx(10) : assigned(1)]. idx unique -> assigned bit
// never affects ordering; equal values tie to smaller idx (numpy first-min).
__device__ __forceinline__ unsigned long long packkey(float x, int idx, unsigned abit) {
    return ((unsigned long long)flip32(x) << 11) |
           ((unsigned long long)idx << 1) | (unsigned long long)abit;
}

// thread's k-th column: [4t .. 4t+3] and [512+4t .. 512+4t+3]
__device__ __forceinline__ int jcol(int tid, int k) {
    return ((k & 4) << 7) + (tid << 2) + (k & 3);
}

// ---------------------------------------------------------------------------
// Jonker-Volgenant shortest-augmenting-path LSA, one CTA per batch. Pure fp32
// (R13-verified on this data). colinfo[j] = {u[row4col[j]] bits, row4col[j]}
// fuses the pop->next-row staging into one LDS.64; mv and the assigned bit
// ride in the packed argmin key. ONE barrier per Dijkstra step.
// ---------------------------------------------------------------------------
__global__ void __launch_bounds__(NT, 1)
solve_kernel(const int* __restrict__ ngt, float* __restrict__ out) {
    const int b = blockIdx.x;
    const int tid = threadIdx.x;
    const int w = tid >> 5;

    __shared__ float s_short[NQ];            // shortest (write-through, for duals)
    __shared__ uint2 s_colinfo[NQ];          // {u_of_row bits, row} per column
    __shared__ unsigned char s_path[NQ];
    __shared__ float s_u[NG];
    __shared__ short s_col4row[NG];
    __shared__ unsigned char s_inSR[NG];
    __shared__ __align__(16) unsigned long long s_pack[4][4];   // [ring][warp]

    float* outi = out + b * NQ;              // per_prop_gt_inds (as float)
    float* outm = out + NB * NQ + b * NQ;    // proposal_matched_mask

    for (int j = tid; j < NQ; j += NT) { outi[j] = 0.0f; outm[j] = 0.0f; }

    const int g = ngt[b];
    if (g <= 0) return;

    const float* __restrict__ cost = g_cost + b * NG * NQ;

    float v_reg[KPT], sh_reg[KPT];
#pragma unroll
    for (int k = 0; k < KPT; ++k) v_reg[k] = 0.0f;
    unsigned amask = 0;                      // assigned bits for my 8 columns

    for (int i = tid; i < g; i += NT) { s_u[i] = 0.0f; s_col4row[i] = -1; }
    if (tid < 16) s_pack[tid >> 2][tid & 3] = ~0ULL;

    int t = 0;   // ring phase, continuous across Dijkstras
    __syncthreads();

    for (int cur = 0; cur < g; ++cur) {
        unsigned scmask = 0;
        float lbest = BIGF;
        int lidx = 0;
#pragma unroll
        for (int k = 0; k < KPT; ++k) sh_reg[k] = BIGF;
        for (int i = tid; i < g; i += NT) s_inSR[i] = (i == cur) ? 1 : 0;
        __syncthreads();

        int i = cur;
        float mv = 0.0f;
        float u_i = 0.0f;                    // u[cur] == 0 before its own solve
        int sink;

        // ---- Dijkstra over columns: ONE barrier per step ----
        while (true) {
            const float scal = mv - u_i;
            const float* __restrict__ crow = cost + i * NQ;

            // 2x coalesced LDG.128 covering my 8 columns
            const float4 f0 = *(const float4*)(crow + (tid << 2));
            const float4 f1 = *(const float4*)(crow + 512 + (tid << 2));
            const float cf[KPT] = {f0.x, f0.y, f0.z, f0.w, f1.x, f1.y, f1.z, f1.w};

#pragma unroll
            for (int k = 0; k < KPT; ++k) {
                if (!((scmask >> k) & 1u)) {
                    const float r = (scal + cf[k]) - v_reg[k];
                    if (r < sh_reg[k]) {
                        const int j = jcol(tid, k);
                        sh_reg[k] = r;
                        s_short[j] = r;
                        s_path[j] = (unsigned char)i;
                        if (r < lbest) { lbest = r; lidx = j; }
                    }
                }
            }
            if (lbest < BIGF) {
                const int lk = ((lidx >> 9) << 2) | (lidx & 3);
                atomicMin(&s_pack[t & 3][w], packkey(lbest, lidx, (amask >> lk) & 1u));
            }
            __syncthreads();

            // all threads combine the 4 per-warp cells
            const unsigned long long* cell = s_pack[t & 3];
            unsigned long long p  = cell[0];
            unsigned long long q1 = cell[1];
            unsigned long long q2 = cell[2];
            unsigned long long q3 = cell[3];
            if (q1 < p) p = q1;
            if (q2 < p) p = q2;
            if (q3 < p) p = q3;
            const int bidx = (int)((p >> 1) & 1023ULL);
            const unsigned abit = (unsigned)(p & 1ULL);

            if (tid < 4) s_pack[(t + 2) & 3][tid] = ~0ULL;   // barrier-ordered reset

            mv = unflip32((unsigned int)(p >> 11));          // exact popped value

            // owner removes the visited column and rescans its registers
            if (((bidx & 511) >> 2) == tid) {
                const int kk = ((bidx >> 9) << 2) | (bidx & 3);
                scmask |= 1u << kk;
                lbest = BIGF; lidx = 0;
#pragma unroll
                for (int k = 0; k < KPT; ++k) {
                    if (!((scmask >> k) & 1u) && sh_reg[k] < lbest) {
                        lbest = sh_reg[k];
                        lidx = jcol(tid, k);
                    }
                }
            }
            ++t;
            if (!abit) { sink = bidx; break; }               // unassigned -> done

            const uint2 ci = s_colinfo[bidx];                // {u bits, row}
            i = (int)ci.y;
            u_i = __uint_as_float(ci.x);
            if (tid == 0) s_inSR[i] = 1;
        }

        // (no barrier needed: all shared writes above are >=1 in-loop barrier old)

        // ---- dual updates (pre-augment col4row) ----
#pragma unroll
        for (int k = 0; k < KPT; ++k) {
            if ((scmask >> k) & 1u) v_reg[k] -= (mv - sh_reg[k]);
        }
        for (int ii = tid; ii < g; ii += NT) {
            if (ii == cur) {
                s_u[ii] += mv;
            } else if (s_inSR[ii]) {
                const int cj = s_col4row[ii];
                const float un = s_u[ii] + (mv - s_short[cj]);
                s_u[ii] = un;
                s_colinfo[cj] = make_uint2(__float_as_uint(un), (unsigned)ii);
            }
        }
        __syncthreads();

        // ---- augment alternating path (serial, short) ----
        if (tid == 0) {
            int j = sink;
            while (true) {
                const int ii = s_path[j];
                s_colinfo[j] = make_uint2(__float_as_uint(s_u[ii]), (unsigned)ii);
                const short nj = s_col4row[ii];
                s_col4row[ii] = (short)j;
                j = nj;
                if (ii == cur) break;
            }
        }
        // sink's owner marks it assigned (uniform: every thread knows sink)
        if (((sink & 511) >> 2) == tid) amask |= 1u << (((sink >> 9) << 2) | (sink & 3));
        __syncthreads();
    }

    // outputs: proposal p = col4row[i] gets index i, mask 1
    for (int i = tid; i < g; i += NT) {
        const int p = s_col4row[i];
        outi[p] = (float)i;
        outm[p] = 1.0f;
    }
}

extern "C" void kernel_launch(void* const* d_in, const int* in_sizes, int n_in,
                              void* d_out, int out_size) {
    const float* obj = (const float*)d_in[1];
    const float* cd  = (const float*)d_in[2];
    const float* gi  = (const float*)d_in[3];
    const int* ngt   = (const int*)d_in[4];
    float* out = (float*)d_out;

    const int total = NB * NG * NQ;
    build_cost_kernel<<<(total + 255) / 256, 256>>>(obj, cd, gi);
    solve_kernel<<<NB, NT>>>(ngt, out);
}